// round 14
// baseline (speedup 1.0000x reference)
#include <cuda_runtime.h>
#include <cuda_bf16.h>
#include <cstdint>

// ---------------------------------------------------------------- constants
constexpr int MTOK = 8192, DIN = 4096, DOUT = 4096;
constexpr int E = 8, DK = 32, R = 16;
constexpr int NPROJ = 640, NPROJ_PAD = 768;
constexpr int GEXT  = 192;                 // ext cols: 128 lora + 1 bias + 63 pad (hi only)
constexpr int EXT0  = 2 * DIN;             // 8192
constexpr int KP2   = 2 * DIN + GEXT;      // 8384: [hi | lo | ext_hi]

// ---------------------------------------------------------------- scratch
__device__ __align__(1024) __nv_bfloat16 g_Xp[(size_t)MTOK * KP2];
__device__ __align__(1024) __nv_bfloat16 g_Wp[(size_t)DOUT * KP2];
__device__ __align__(1024) __nv_bfloat16 g_Pp[(size_t)NPROJ_PAD * DIN];
__device__ __align__(1024) float         g_P [(size_t)MTOK * NPROJ_PAD];

// ---------------------------------------------------------------- ptx utils
__device__ __forceinline__ uint32_t smem_u32(const void* p) {
    uint32_t a;
    asm("{ .reg .u64 t; cvta.to.shared.u64 t, %1; cvt.u32.u64 %0, t; }" : "=r"(a) : "l"(p));
    return a;
}
__device__ __forceinline__ uint32_t ctarank() {
    uint32_t r; asm("mov.u32 %0, %%cluster_ctarank;" : "=r"(r)); return r;
}
__device__ __forceinline__ void cluster_sync() {
    asm volatile("barrier.cluster.arrive.aligned;" ::: "memory");
    asm volatile("barrier.cluster.wait.aligned;" ::: "memory");
}
__device__ __forceinline__ void mbar_init(uint32_t a, uint32_t c) {
    asm volatile("mbarrier.init.shared.b64 [%0], %1;" :: "r"(a), "r"(c) : "memory");
}
__device__ __forceinline__ void mbar_inval(uint32_t a) {
    asm volatile("mbarrier.inval.shared.b64 [%0];" :: "r"(a) : "memory");
}
__device__ __forceinline__ void mbar_arrive_rank0(uint32_t a) {
    asm volatile("{ .reg .b32 ra; mapa.shared::cluster.u32 ra, %0, 0;"
                 " mbarrier.arrive.shared::cluster.b64 _, [ra]; }" :: "r"(a) : "memory");
}
__device__ __forceinline__ void mbar_wait(uint32_t a, uint32_t parity) {
    asm volatile("{ .reg .pred P;\n"
                 "W%=: mbarrier.try_wait.parity.acquire.cta.shared::cta.b64 P, [%0], %1, 0x989680;\n"
                 "@P bra D%=;\n bra W%=;\nD%=: }"
                 :: "r"(a), "r"(parity) : "memory");
}
__device__ __forceinline__ void cpa16(uint32_t s, const void* g) {
    asm volatile("cp.async.cg.shared.global [%0], [%1], 16;" :: "r"(s), "l"(g));
}
__device__ __forceinline__ void cp_commit() { asm volatile("cp.async.commit_group;"); }
template <int N> __device__ __forceinline__ void cp_wait() {
    asm volatile("cp.async.wait_group %0;" :: "n"(N));
}
__device__ __forceinline__ void fence_async() {
    asm volatile("fence.proxy.async.shared::cta;" ::: "memory");
}
constexpr uint64_t DESC_BASE = (2ull<<61) | (1ull<<46) | (64ull<<32) | (1ull<<16);
__device__ __forceinline__ uint64_t mk_desc(uint32_t a) { return DESC_BASE | ((a >> 4) & 0x3FFF); }
constexpr uint32_t IDESC_MAIN = (1u<<4) | (1u<<7) | (1u<<10) | ((256/8)<<17) | ((256/16)<<24);
constexpr uint32_t IDESC_PROJ = (1u<<4) | (1u<<7) | (1u<<10) | ((128/8)<<17) | ((256/16)<<24);

__device__ __forceinline__ void mma_cg2(uint32_t d, uint64_t ad, uint64_t bd,
                                        uint32_t idesc, uint32_t en) {
    asm volatile("{ .reg .pred p; setp.ne.u32 p, %5, 0;\n"
                 "tcgen05.mma.cta_group::2.kind::f16 [%0], %1, %2, %3,"
                 " {%4,%4,%4,%4,%4,%4,%4,%4}, p; }"
                 :: "r"(d), "l"(ad), "l"(bd), "r"(idesc), "r"(0u), "r"(en) : "memory");
}

// ---------------------------------------------------------------- split helpers
__device__ __forceinline__ void split2(float v, __nv_bfloat16& hi, __nv_bfloat16& lo) {
    hi = __float2bfloat16(v);
    lo = __float2bfloat16(v - __bfloat162float(hi));
}
__device__ __forceinline__ uint32_t pack2(__nv_bfloat16 a, __nv_bfloat16 b) {
    __nv_bfloat162 t(a, b);
    return *reinterpret_cast<uint32_t*>(&t);
}

// ---------------------------------------------------------------- merged split x+W
__global__ void __launch_bounds__(256) split_xw_kernel(const float* __restrict__ x,
                                                       const float* __restrict__ W) {
    const int row = blockIdx.x;
    const float* src;
    __nv_bfloat16* dst;
    if (row < MTOK) { src = x + (size_t)row * DIN; dst = g_Xp + (size_t)row * KP2; }
    else { src = W + (size_t)(row - MTOK) * DIN; dst = g_Wp + (size_t)(row - MTOK) * KP2; }
    const int t = threadIdx.x;
    float4 v[4];
#pragma unroll
    for (int j = 0; j < 4; j++)
        v[j] = *reinterpret_cast<const float4*>(src + (t + j * 256) * 4);
#pragma unroll
    for (int j = 0; j < 4; j++) {
        int col = (t + j * 256) * 4;
        __nv_bfloat16 h0,l0,h1,l1,h2,l2,h3,l3;
        split2(v[j].x,h0,l0); split2(v[j].y,h1,l1); split2(v[j].z,h2,l2); split2(v[j].w,h3,l3);
        *reinterpret_cast<uint2*>(dst + col)       = make_uint2(pack2(h0,h1), pack2(h2,h3));
        *reinterpret_cast<uint2*>(dst + DIN + col) = make_uint2(pack2(l0,l1), pack2(l2,l3));
    }
}

// ---------------------------------------------------------------- pack kernels
__global__ void split_proj_kernel(const float* __restrict__ Wq,
                                  const float* __restrict__ Wk,
                                  const float* __restrict__ A) {
    size_t t = (size_t)blockIdx.x * 256 + threadIdx.x;
    if (t >= (size_t)NPROJ_PAD * DIN / 4) return;
    int row = (int)(t / (DIN / 4)), col = (int)(t % (DIN / 4)) * 4;
    float4 v = make_float4(0.f, 0.f, 0.f, 0.f);
    if (row < 256)      v = *reinterpret_cast<const float4*>(Wq + (size_t)row * DIN + col);
    else if (row < 512) v = *reinterpret_cast<const float4*>(Wk + (size_t)(row - 256) * DIN + col);
    else if (row < 640) v = *reinterpret_cast<const float4*>(A  + (size_t)(row - 512) * DIN + col);
    *reinterpret_cast<uint2*>(g_Pp + (size_t)row * DIN + col) =
        make_uint2(pack2(__float2bfloat16(v.x), __float2bfloat16(v.y)),
                   pack2(__float2bfloat16(v.z), __float2bfloat16(v.w)));
}

__global__ void pack_b2_kernel(const float* __restrict__ Bm, const float* __restrict__ b) {
    int idx = blockIdx.x * 256 + threadIdx.x;
    if (idx >= DOUT * GEXT) return;
    int o = idx / GEXT, j = idx - o * GEXT;
    float v = 0.f;
    if (j < E * R) { int e = j >> 4, r = j & 15; v = Bm[((size_t)e * DOUT + o) * R + r]; }
    else if (j == E * R) v = b[o];
    g_Wp[(size_t)o * KP2 + EXT0 + j] = __float2bfloat16(v);
}

// ---------------------------------------------------------------- routing (ext hi only)
__global__ void routing_kernel() {
    int warp = (blockIdx.x * blockDim.x + threadIdx.x) >> 5;
    int lane = threadIdx.x & 31;
    if (warp >= MTOK) return;
    const float* Pt = g_P + (size_t)warp * NPROJ_PAD;
    float s[E];
#pragma unroll
    for (int e = 0; e < E; e++) {
        float p = Pt[e * DK + lane] * Pt[E * DK + e * DK + lane];
#pragma unroll
        for (int o = 16; o > 0; o >>= 1) p += __shfl_xor_sync(0xffffffffu, p, o);
        s[e] = p * 0.17677669529663687f;
    }
    float m = s[0];
#pragma unroll
    for (int e = 1; e < E; e++) m = fmaxf(m, s[e]);
    float Z = 0.f;
#pragma unroll
    for (int e = 0; e < E; e++) { s[e] = __expf(s[e] - m); Z += s[e]; }
    float inv = 1.f / Z;

    __nv_bfloat16* Gt = g_Xp + (size_t)warp * KP2 + EXT0;
#pragma unroll
    for (int j = lane; j < GEXT; j += 32) {
        float g = 0.f;
        if (j < E * R)       g = s[j >> 4] * inv * Pt[2 * E * DK + j];
        else if (j == E * R) g = 1.0f;
        Gt[j] = __float2bfloat16(g);
    }
}

// ---------------------------------------------------------------- proj GEMM (TN=128)
// 256x128 per cg2 pair -> 384 CTAs (192 pairs), finer wave granularity.
__global__ void __cluster_dims__(2, 1, 1) __launch_bounds__(256, 1)
gemm_proj_kernel() {
#if defined(__CUDA_ARCH_FEAT_SM103_ALL)
    constexpr int NST = 4, NCH = DIN / 64, STAGE = 24576;   // A 16KB + B 8KB
    constexpr int SLAST = (NCH - 1) & (NST - 1);            // 3
    constexpr uint32_t FINPAR = (((NCH - 1 - SLAST) / NST + 1) - 1) & 1;  // 1

    extern __shared__ char smem[];
    const uint32_t sbase = smem_u32(smem);
    const int tid = threadIdx.x, wid = tid >> 5, lane = tid & 31;
    const uint32_t rank = ctarank();
    const int n_tile = blockIdx.x >> 1, m_tile = blockIdx.y;
    const uint32_t FULL0 = sbase + 8, MMAB0 = sbase + 40;

    if (tid == 0)
        for (int s = 0; s < NST; s++) { mbar_init(FULL0 + s * 8, 2); mbar_init(MMAB0 + s * 8, 1); }
    if (wid == 0)
        asm volatile("tcgen05.alloc.cta_group::2.sync.aligned.shared::cta.b32 [%0], %1;"
                     :: "r"(sbase), "r"(512) : "memory");
    __syncthreads();
    uint32_t tmem;
    asm volatile("ld.shared.b32 %0, [%1];" : "=r"(tmem) : "r"(sbase));
    cluster_sync();

    const __nv_bfloat16* Arow = g_Xp + (size_t)(m_tile * 256 + rank * 128) * KP2;
    const __nv_bfloat16* Brow = g_Pp + (size_t)(n_tile * 128 + rank * 64) * DIN;

    auto fill = [&](int chunk) {
        const int kb = chunk * 64;
        const uint32_t st = sbase + 1024 + (chunk & (NST - 1)) * STAGE;
#pragma unroll
        for (int p = 0; p < 4; p++) {                    // A: 128 rows
            int q = p * 256 + tid, r = q >> 3, c = q & 7;
            uint32_t off = (uint32_t)(r * 128 + c * 16);
            uint32_t sw = off ^ ((off >> 3) & 0x70);
            cpa16(st + sw, Arow + (size_t)r * KP2 + kb + c * 8);
        }
#pragma unroll
        for (int p = 0; p < 2; p++) {                    // B: 64 rows
            int q = p * 256 + tid, r = q >> 3, c = q & 7;
            uint32_t off = (uint32_t)(r * 128 + c * 16);
            uint32_t sw = off ^ ((off >> 3) & 0x70);
            cpa16(st + 16384 + sw, Brow + (size_t)r * DIN + kb + c * 8);
        }
        cp_commit();
    };

    uint32_t fph[NST] = {}, mph[NST] = {};
    fill(0); fill(1); fill(2);
    for (int i = 0; i < NCH; i++) {
        const int s = i & (NST - 1), rem = NCH - 1 - i;
        if (rem >= 2) cp_wait<2>(); else if (rem == 1) cp_wait<1>(); else cp_wait<0>();
        __syncthreads();
        if (tid == 0) { fence_async(); mbar_arrive_rank0(FULL0 + s * 8); }
        if (rank == 0 && tid == 0) {
            mbar_wait(FULL0 + s * 8, fph[s]); fph[s] ^= 1;
            const uint32_t st = sbase + 1024 + s * STAGE;
            uint64_t ad = mk_desc(st), bd = mk_desc(st + 16384);
#pragma unroll
            for (int kk = 0; kk < 4; kk++)
                mma_cg2(tmem, ad + kk * 2, bd + kk * 2, IDESC_PROJ, (i > 0) || (kk > 0));
            asm volatile("tcgen05.commit.cta_group::2.mbarrier::arrive::one.shared::cluster.multicast::cluster.b64 [%0], %1;"
                         :: "r"(MMAB0 + s * 8), "h"((uint16_t)3) : "memory");
        }
        const int j = i + NST - 1;
        if (j < NCH) {
            const int s2 = j & (NST - 1);
            if (j >= NST) { mbar_wait(MMAB0 + s2 * 8, mph[s2]); mph[s2] ^= 1; }
            fill(j);
        }
    }
    mbar_wait(MMAB0 + SLAST * 8, FINPAR);
    asm volatile("tcgen05.fence::after_thread_sync;" ::: "memory");

    // epilogue: 128 rows x 128 cols per CTA; warp w -> rows (w&3)*32, col half (w>>2)*64
    {
        const int gm = m_tile * 256 + (int)rank * 128 + (wid & 3) * 32 + lane;
        float* crow = g_P + (size_t)gm * NPROJ_PAD + n_tile * 128 + (wid >> 2) * 64;
        const uint32_t cb0 = tmem + (uint32_t)((wid >> 2) * 64);
#pragma unroll
        for (int cb = 0; cb < 64; cb += 32) {
            uint32_t d[32];
            asm volatile("tcgen05.ld.sync.aligned.32x32b.x32.b32 "
                "{%0,%1,%2,%3,%4,%5,%6,%7,%8,%9,%10,%11,%12,%13,%14,%15,"
                "%16,%17,%18,%19,%20,%21,%22,%23,%24,%25,%26,%27,%28,%29,%30,%31}, [%32];"
                : "=r"(d[0]),"=r"(d[1]),"=r"(d[2]),"=r"(d[3]),"=r"(d[4]),"=r"(d[5]),"=r"(d[6]),"=r"(d[7]),
                  "=r"(d[8]),"=r"(d[9]),"=r"(d[10]),"=r"(d[11]),"=r"(d[12]),"=r"(d[13]),"=r"(d[14]),"=r"(d[15]),
                  "=r"(d[16]),"=r"(d[17]),"=r"(d[18]),"=r"(d[19]),"=r"(d[20]),"=r"(d[21]),"=r"(d[22]),"=r"(d[23]),
                  "=r"(d[24]),"=r"(d[25]),"=r"(d[26]),"=r"(d[27]),"=r"(d[28]),"=r"(d[29]),"=r"(d[30]),"=r"(d[31])
                : "r"(cb0 + cb));
            asm volatile("tcgen05.wait::ld.sync.aligned;" ::: "memory");
#pragma unroll
            for (int c = 0; c < 32; c += 4)
                *reinterpret_cast<float4*>(crow + cb + c) =
                    make_float4(__uint_as_float(d[c]), __uint_as_float(d[c+1]),
                                __uint_as_float(d[c+2]), __uint_as_float(d[c+3]));
        }
    }
    __syncthreads();
    if (tid == 0) {
        for (int s = 0; s < NST; s++) { mbar_inval(FULL0 + s * 8); mbar_inval(MMAB0 + s * 8); }
    }
    __syncthreads();
    if (wid == 0) {
        asm volatile("tcgen05.relinquish_alloc_permit.cta_group::2.sync.aligned;");
        asm volatile("tcgen05.dealloc.cta_group::2.sync.aligned.b32 %0, %1;" :: "r"(tmem), "r"(512));
    }
    cluster_sync();
#endif
}

// ---------------------------------------------------------------- main GEMM (R13 unchanged)
__global__ void __cluster_dims__(2, 1, 1) __launch_bounds__(256, 1)
gemm_main_kernel(float* __restrict__ Cg) {
#if defined(__CUDA_ARCH_FEAT_SM103_ALL)
    constexpr int NST = 2;
    constexpr int NCH = DIN / 64 + GEXT / 64;       // 67
    constexpr int STAGE = 98304;
    constexpr int A_HI = 0, A_LO = 16384, B_HI = 32768, B_LO = 65536;
    constexpr int SLAST = (NCH - 1) & (NST - 1);    // 0
    constexpr uint32_t FINPAR = (((NCH - 1 - SLAST) / NST + 1) - 1) & 1;  // 1

    extern __shared__ char smem[];
    const uint32_t sbase = smem_u32(smem);
    const int tid = threadIdx.x, wid = tid >> 5, lane = tid & 31;
    const uint32_t rank = ctarank();
    const int n_tile = blockIdx.x >> 1, m_tile = blockIdx.y;
    const uint32_t FULL0 = sbase + 8, MMAB0 = sbase + 40;

    if (tid == 0)
        for (int s = 0; s < NST; s++) { mbar_init(FULL0 + s * 8, 2); mbar_init(MMAB0 + s * 8, 1); }
    if (wid == 0)
        asm volatile("tcgen05.alloc.cta_group::2.sync.aligned.shared::cta.b32 [%0], %1;"
                     :: "r"(sbase), "r"(512) : "memory");
    __syncthreads();
    uint32_t tmem;
    asm volatile("ld.shared.b32 %0, [%1];" : "=r"(tmem) : "r"(sbase));
    cluster_sync();

    const int arow0 = m_tile * 256 + (int)rank * 128;
    const int brow0 = n_tile * 512 + (int)rank * 128;
    const __nv_bfloat16* Arow = g_Xp + (size_t)arow0 * KP2;
    const __nv_bfloat16* Brow = g_Wp + (size_t)brow0 * KP2;

    auto load_tile = [&](uint32_t sdst, const __nv_bfloat16* gsrc) {
#pragma unroll
        for (int p = 0; p < 4; p++) {
            int q = p * 256 + tid, r = q >> 3, c = q & 7;
            uint32_t off = (uint32_t)(r * 128 + c * 16);
            uint32_t sw = off ^ ((off >> 3) & 0x70);
            cpa16(sdst + sw, gsrc + (size_t)r * KP2 + c * 8);
        }
    };

    auto fill = [&](int chunk) {
        const uint32_t st = sbase + 1024 + (chunk & (NST - 1)) * STAGE;
        if (chunk < 64) {
            const int kb = chunk * 64;
            load_tile(st + A_HI, Arow + kb);
            load_tile(st + A_LO, Arow + kb + DIN);
#pragma unroll
            for (int h = 0; h < 2; h++) {
                const __nv_bfloat16* Bh = Brow + (size_t)(h * 256) * KP2;
                load_tile(st + B_HI + h * 16384, Bh + kb);
                load_tile(st + B_LO + h * 16384, Bh + kb + DIN);
            }
        } else {
            const int kb = EXT0 + (chunk - 64) * 64;
            load_tile(st + A_HI, Arow + kb);
#pragma unroll
            for (int h = 0; h < 2; h++)
                load_tile(st + B_HI + h * 16384, Brow + (size_t)(h * 256) * KP2 + kb);
        }
        cp_commit();
    };

    uint32_t fph[NST] = {}, mph[NST] = {};
    fill(0);
    for (int i = 0; i < NCH; i++) {
        const int s = i & (NST - 1);
        cp_wait<0>();
        __syncthreads();
        if (tid == 0) { fence_async(); mbar_arrive_rank0(FULL0 + s * 8); }
        if (rank == 0 && tid == 0) {
            mbar_wait(FULL0 + s * 8, fph[s]); fph[s] ^= 1;
            const uint32_t st = sbase + 1024 + s * STAGE;
            uint64_t ahi = mk_desc(st + A_HI), alo = mk_desc(st + A_LO);
#pragma unroll
            for (int h = 0; h < 2; h++) {
                uint64_t bhi = mk_desc(st + B_HI + h * 16384);
                uint64_t blo = mk_desc(st + B_LO + h * 16384);
                uint32_t dh = tmem + h * 256;
#pragma unroll
                for (int kk = 0; kk < 4; kk++) {
                    uint32_t en = ((i > 0) || (kk > 0)) ? 1u : 0u;
                    mma_cg2(dh, ahi + kk * 2, bhi + kk * 2, IDESC_MAIN, en);
                    if (i < 64) {
                        mma_cg2(dh, alo + kk * 2, bhi + kk * 2, IDESC_MAIN, 1u);
                        mma_cg2(dh, ahi + kk * 2, blo + kk * 2, IDESC_MAIN, 1u);
                    }
                }
            }
            asm volatile("tcgen05.commit.cta_group::2.mbarrier::arrive::one.shared::cluster.multicast::cluster.b64 [%0], %1;"
                         :: "r"(MMAB0 + s * 8), "h"((uint16_t)3) : "memory");
        }
        const int j = i + 1;
        if (j < NCH) {
            const int s2 = j & (NST - 1);
            if (j >= NST) { mbar_wait(MMAB0 + s2 * 8, mph[s2]); mph[s2] ^= 1; }
            fill(j);
        }
    }
    mbar_wait(MMAB0 + SLAST * 8, FINPAR);
    asm volatile("tcgen05.fence::after_thread_sync;" ::: "memory");

    // epilogue
    {
        const int gm = arow0 + (wid & 3) * 32 + lane;
        float* crow = Cg + (size_t)gm * DOUT + n_tile * 512 + (wid >> 2) * 256;
        const uint32_t cb0 = tmem + (uint32_t)((wid >> 2) * 256);
#pragma unroll
        for (int cb = 0; cb < 256; cb += 32) {
            uint32_t d[32];
            asm volatile("tcgen05.ld.sync.aligned.32x32b.x32.b32 "
                "{%0,%1,%2,%3,%4,%5,%6,%7,%8,%9,%10,%11,%12,%13,%14,%15,"
                "%16,%17,%18,%19,%20,%21,%22,%23,%24,%25,%26,%27,%28,%29,%30,%31}, [%32];"
                : "=r"(d[0]),"=r"(d[1]),"=r"(d[2]),"=r"(d[3]),"=r"(d[4]),"=r"(d[5]),"=r"(d[6]),"=r"(d[7]),
                  "=r"(d[8]),"=r"(d[9]),"=r"(d[10]),"=r"(d[11]),"=r"(d[12]),"=r"(d[13]),"=r"(d[14]),"=r"(d[15]),
                  "=r"(d[16]),"=r"(d[17]),"=r"(d[18]),"=r"(d[19]),"=r"(d[20]),"=r"(d[21]),"=r"(d[22]),"=r"(d[23]),
                  "=r"(d[24]),"=r"(d[25]),"=r"(d[26]),"=r"(d[27]),"=r"(d[28]),"=r"(d[29]),"=r"(d[30]),"=r"(d[31])
                : "r"(cb0 + cb));
            asm volatile("tcgen05.wait::ld.sync.aligned;" ::: "memory");
#pragma unroll
            for (int c = 0; c < 32; c += 4)
                *reinterpret_cast<float4*>(crow + cb + c) =
                    make_float4(__uint_as_float(d[c]), __uint_as_float(d[c+1]),
                                __uint_as_float(d[c+2]), __uint_as_float(d[c+3]));
        }
    }
    __syncthreads();
    if (tid == 0) {
        for (int s = 0; s < NST; s++) { mbar_inval(FULL0 + s * 8); mbar_inval(MMAB0 + s * 8); }
    }
    __syncthreads();
    if (wid == 0) {
        asm volatile("tcgen05.relinquish_alloc_permit.cta_group::2.sync.aligned;");
        asm volatile("tcgen05.dealloc.cta_group::2.sync.aligned.b32 %0, %1;" :: "r"(tmem), "r"(512));
    }
    cluster_sync();
#endif
}

// ---------------------------------------------------------------- launch
// Inputs (metadata order): x, W, b, Wq, Wk, A, Bm
extern "C" void kernel_launch(void* const* d_in, const int* in_sizes, int n_in,
                              void* d_out, int out_size) {
    const float* x  = (const float*)d_in[0];
    const float* W  = (const float*)d_in[1];
    const float* b  = (const float*)d_in[2];
    const float* Wq = (const float*)d_in[3];
    const float* Wk = (const float*)d_in[4];
    const float* A  = (const float*)d_in[5];
    const float* Bm = (const float*)d_in[6];
    float* out = (float*)d_out;

    constexpr int SMEM0 = 1024 + 4 * 24576;    // 99328
    constexpr int SMEM1 = 1024 + 2 * 98304;    // 197632
    cudaFuncSetAttribute(gemm_proj_kernel, cudaFuncAttributeMaxDynamicSharedMemorySize, SMEM0);
    cudaFuncSetAttribute(gemm_main_kernel, cudaFuncAttributeMaxDynamicSharedMemorySize, SMEM1);

    split_xw_kernel  <<<MTOK + DOUT, 256>>>(x, W);
    split_proj_kernel<<<(int)(((size_t)NPROJ_PAD * DIN / 4 + 255) / 256), 256>>>(Wq, Wk, A);
    pack_b2_kernel   <<<(DOUT * GEXT + 255) / 256, 256>>>(Bm, b);

    // projections P = x_hi @ [Wq;Wk;A]_hi^T  (TN=128, 192 pairs)
    gemm_proj_kernel<<<dim3(2 * (NPROJ_PAD / 128), MTOK / 256), 256, SMEM0>>>();

    // routing -> G ext cols (hi only) of g_Xp
    routing_kernel<<<(MTOK * 32) / 256, 256>>>();

    // out = x @ W^T + G @ B2^T (+bias)
    gemm_main_kernel<<<dim3(2 * (DOUT / 512), MTOK / 256), 256, SMEM1>>>(out);
}

// round 16
// speedup vs baseline: 1.0648x; 1.0648x over previous
#include <cuda_runtime.h>
#include <cuda_bf16.h>
#include <cstdint>

// ---------------------------------------------------------------- constants
constexpr int MTOK = 8192, DIN = 4096, DOUT = 4096;
constexpr int E = 8, DK = 32, R = 16;
constexpr int NPROJ = 640, NPROJ_PAD = 768;
constexpr int GEXT  = 192;                 // ext cols: 128 lora + 1 bias + 63 pad (hi only)
constexpr int EXT0  = 2 * DIN;             // 8192
constexpr int KP2   = 2 * DIN + GEXT;      // 8384: [hi | lo | ext_hi]

// ---------------------------------------------------------------- scratch
__device__ __align__(1024) __nv_bfloat16 g_Xp[(size_t)MTOK * KP2];
__device__ __align__(1024) __nv_bfloat16 g_Wp[(size_t)DOUT * KP2];
__device__ __align__(1024) __nv_bfloat16 g_Pp[(size_t)NPROJ_PAD * DIN];
__device__ __align__(1024) float         g_P [(size_t)MTOK * NPROJ_PAD];

// ---------------------------------------------------------------- ptx utils
__device__ __forceinline__ uint32_t smem_u32(const void* p) {
    uint32_t a;
    asm("{ .reg .u64 t; cvta.to.shared.u64 t, %1; cvt.u32.u64 %0, t; }" : "=r"(a) : "l"(p));
    return a;
}
__device__ __forceinline__ uint32_t ctarank() {
    uint32_t r; asm("mov.u32 %0, %%cluster_ctarank;" : "=r"(r)); return r;
}
__device__ __forceinline__ void cluster_sync() {
    asm volatile("barrier.cluster.arrive.aligned;" ::: "memory");
    asm volatile("barrier.cluster.wait.aligned;" ::: "memory");
}
__device__ __forceinline__ void mbar_init(uint32_t a, uint32_t c) {
    asm volatile("mbarrier.init.shared.b64 [%0], %1;" :: "r"(a), "r"(c) : "memory");
}
__device__ __forceinline__ void mbar_inval(uint32_t a) {
    asm volatile("mbarrier.inval.shared.b64 [%0];" :: "r"(a) : "memory");
}
__device__ __forceinline__ void mbar_arrive_rank0(uint32_t a) {
    asm volatile("{ .reg .b32 ra; mapa.shared::cluster.u32 ra, %0, 0;"
                 " mbarrier.arrive.shared::cluster.b64 _, [ra]; }" :: "r"(a) : "memory");
}
__device__ __forceinline__ void mbar_wait(uint32_t a, uint32_t parity) {
    asm volatile("{ .reg .pred P;\n"
                 "W%=: mbarrier.try_wait.parity.acquire.cta.shared::cta.b64 P, [%0], %1, 0x989680;\n"
                 "@P bra D%=;\n bra W%=;\nD%=: }"
                 :: "r"(a), "r"(parity) : "memory");
}
__device__ __forceinline__ void cpa16(uint32_t s, const void* g) {
    asm volatile("cp.async.cg.shared.global [%0], [%1], 16;" :: "r"(s), "l"(g));
}
__device__ __forceinline__ void cp_commit() { asm volatile("cp.async.commit_group;"); }
template <int N> __device__ __forceinline__ void cp_wait() {
    asm volatile("cp.async.wait_group %0;" :: "n"(N));
}
__device__ __forceinline__ void fence_async() {
    asm volatile("fence.proxy.async.shared::cta;" ::: "memory");
}
constexpr uint64_t DESC_BASE = (2ull<<61) | (1ull<<46) | (64ull<<32) | (1ull<<16);
__device__ __forceinline__ uint64_t mk_desc(uint32_t a) { return DESC_BASE | ((a >> 4) & 0x3FFF); }
constexpr uint32_t IDESC_MAIN = (1u<<4) | (1u<<7) | (1u<<10) | ((256/8)<<17) | ((256/16)<<24);

__device__ __forceinline__ void mma_cg2(uint32_t d, uint64_t ad, uint64_t bd, uint32_t en) {
    asm volatile("{ .reg .pred p; setp.ne.u32 p, %5, 0;\n"
                 "tcgen05.mma.cta_group::2.kind::f16 [%0], %1, %2, %3,"
                 " {%4,%4,%4,%4,%4,%4,%4,%4}, p; }"
                 :: "r"(d), "l"(ad), "l"(bd), "r"(IDESC_MAIN), "r"(0u), "r"(en) : "memory");
}

// ---------------------------------------------------------------- split helpers
__device__ __forceinline__ void split2(float v, __nv_bfloat16& hi, __nv_bfloat16& lo) {
    hi = __float2bfloat16(v);
    lo = __float2bfloat16(v - __bfloat162float(hi));
}
__device__ __forceinline__ uint32_t pack2(__nv_bfloat16 a, __nv_bfloat16 b) {
    __nv_bfloat162 t(a, b);
    return *reinterpret_cast<uint32_t*>(&t);
}

// ---------------------------------------------------------------- merged split x+W
__global__ void __launch_bounds__(256) split_xw_kernel(const float* __restrict__ x,
                                                       const float* __restrict__ W) {
    const int row = blockIdx.x;
    const float* src;
    __nv_bfloat16* dst;
    if (row < MTOK) { src = x + (size_t)row * DIN; dst = g_Xp + (size_t)row * KP2; }
    else { src = W + (size_t)(row - MTOK) * DIN; dst = g_Wp + (size_t)(row - MTOK) * KP2; }
    const int t = threadIdx.x;
    float4 v[4];
#pragma unroll
    for (int j = 0; j < 4; j++)
        v[j] = *reinterpret_cast<const float4*>(src + (t + j * 256) * 4);
#pragma unroll
    for (int j = 0; j < 4; j++) {
        int col = (t + j * 256) * 4;
        __nv_bfloat16 h0,l0,h1,l1,h2,l2,h3,l3;
        split2(v[j].x,h0,l0); split2(v[j].y,h1,l1); split2(v[j].z,h2,l2); split2(v[j].w,h3,l3);
        *reinterpret_cast<uint2*>(dst + col)       = make_uint2(pack2(h0,h1), pack2(h2,h3));
        *reinterpret_cast<uint2*>(dst + DIN + col) = make_uint2(pack2(l0,l1), pack2(l2,l3));
    }
}

// ---------------------------------------------------------------- pack kernels
__global__ void split_proj_kernel(const float* __restrict__ Wq,
                                  const float* __restrict__ Wk,
                                  const float* __restrict__ A) {
    size_t t = (size_t)blockIdx.x * 256 + threadIdx.x;
    if (t >= (size_t)NPROJ_PAD * DIN / 4) return;
    int row = (int)(t / (DIN / 4)), col = (int)(t % (DIN / 4)) * 4;
    float4 v = make_float4(0.f, 0.f, 0.f, 0.f);
    if (row < 256)      v = *reinterpret_cast<const float4*>(Wq + (size_t)row * DIN + col);
    else if (row < 512) v = *reinterpret_cast<const float4*>(Wk + (size_t)(row - 256) * DIN + col);
    else if (row < 640) v = *reinterpret_cast<const float4*>(A  + (size_t)(row - 512) * DIN + col);
    *reinterpret_cast<uint2*>(g_Pp + (size_t)row * DIN + col) =
        make_uint2(pack2(__float2bfloat16(v.x), __float2bfloat16(v.y)),
                   pack2(__float2bfloat16(v.z), __float2bfloat16(v.w)));
}

__global__ void pack_b2_kernel(const float* __restrict__ Bm, const float* __restrict__ b) {
    int idx = blockIdx.x * 256 + threadIdx.x;
    if (idx >= DOUT * GEXT) return;
    int o = idx / GEXT, j = idx - o * GEXT;
    float v = 0.f;
    if (j < E * R) { int e = j >> 4, r = j & 15; v = Bm[((size_t)e * DOUT + o) * R + r]; }
    else if (j == E * R) v = b[o];
    g_Wp[(size_t)o * KP2 + EXT0 + j] = __float2bfloat16(v);
}

// ---------------------------------------------------------------- routing (ext hi only)
__global__ void routing_kernel() {
    int warp = (blockIdx.x * blockDim.x + threadIdx.x) >> 5;
    int lane = threadIdx.x & 31;
    if (warp >= MTOK) return;
    const float* Pt = g_P + (size_t)warp * NPROJ_PAD;
    float s[E];
#pragma unroll
    for (int e = 0; e < E; e++) {
        float p = Pt[e * DK + lane] * Pt[E * DK + e * DK + lane];
#pragma unroll
        for (int o = 16; o > 0; o >>= 1) p += __shfl_xor_sync(0xffffffffu, p, o);
        s[e] = p * 0.17677669529663687f;
    }
    float m = s[0];
#pragma unroll
    for (int e = 1; e < E; e++) m = fmaxf(m, s[e]);
    float Z = 0.f;
#pragma unroll
    for (int e = 0; e < E; e++) { s[e] = __expf(s[e] - m); Z += s[e]; }
    float inv = 1.f / Z;

    __nv_bfloat16* Gt = g_Xp + (size_t)warp * KP2 + EXT0;
#pragma unroll
    for (int j = lane; j < GEXT; j += 32) {
        float g = 0.f;
        if (j < E * R)       g = s[j >> 4] * inv * Pt[2 * E * DK + j];
        else if (j == E * R) g = 1.0f;
        Gt[j] = __float2bfloat16(g);
    }
}

// ---------------------------------------------------------------- proj GEMM
// TN=256, BK=128 (two 64-col sub-tiles), NCH=32, NST=3.
// Prefetch depth = 2 fills  =>  steady-state gate is cp_wait<1> (R15 bugfix).
__global__ void __cluster_dims__(2, 1, 1) __launch_bounds__(256, 1)
gemm_proj_kernel() {
#if defined(__CUDA_ARCH_FEAT_SM103_ALL)
    constexpr int NST = 3, NCH = DIN / 128;      // 32 chunks of 128 K-cols
    constexpr int STAGE = 65536;                  // A 2x16KB + B 2x16KB
    constexpr int SLAST = (NCH - 1) % NST;        // 1
    constexpr uint32_t FINPAR = 0;                // slot1: 11 commits -> (11-1)&1

    extern __shared__ char smem[];
    const uint32_t sbase = smem_u32(smem);
    const int tid = threadIdx.x, wid = tid >> 5, lane = tid & 31;
    const uint32_t rank = ctarank();
    const int n_tile = blockIdx.x >> 1, m_tile = blockIdx.y;
    const uint32_t FULL0 = sbase + 8, MMAB0 = sbase + 40;

    if (tid == 0)
        for (int s = 0; s < NST; s++) { mbar_init(FULL0 + s * 8, 2); mbar_init(MMAB0 + s * 8, 1); }
    if (wid == 0)
        asm volatile("tcgen05.alloc.cta_group::2.sync.aligned.shared::cta.b32 [%0], %1;"
                     :: "r"(sbase), "r"(512) : "memory");
    __syncthreads();
    uint32_t tmem;
    asm volatile("ld.shared.b32 %0, [%1];" : "=r"(tmem) : "r"(sbase));
    cluster_sync();

    const __nv_bfloat16* Arow = g_Xp + (size_t)(m_tile * 256 + rank * 128) * KP2;
    const __nv_bfloat16* Brow = g_Pp + (size_t)(n_tile * 256 + rank * 128) * DIN;

    auto load_tile = [&](uint32_t sdst, const __nv_bfloat16* gsrc, int ld) {
#pragma unroll
        for (int p = 0; p < 4; p++) {
            int q = p * 256 + tid, r = q >> 3, c = q & 7;
            uint32_t off = (uint32_t)(r * 128 + c * 16);
            uint32_t sw = off ^ ((off >> 3) & 0x70);
            cpa16(sdst + sw, gsrc + (size_t)r * ld + c * 8);
        }
    };

    auto fill = [&](int chunk) {
        const int kb = chunk * 128;
        const uint32_t st = sbase + 1024 + (chunk % NST) * STAGE;
#pragma unroll
        for (int t2 = 0; t2 < 2; t2++) {
            load_tile(st + t2 * 16384,         Arow + kb + t2 * 64, KP2);
            load_tile(st + 32768 + t2 * 16384, Brow + kb + t2 * 64, DIN);
        }
        cp_commit();
    };

    uint32_t fph[NST] = {}, mph[NST] = {};
    fill(0); fill(1);                       // prefetch depth = 2
    for (int i = 0; i < NCH; i++) {
        const int s = i % NST, rem = NCH - 1 - i;
        // FIX: with 2 prefetched fills, exactly 1 group is newer than chunk i.
        if (rem >= 1) cp_wait<1>(); else cp_wait<0>();
        __syncthreads();
        if (tid == 0) { fence_async(); mbar_arrive_rank0(FULL0 + s * 8); }
        if (rank == 0 && tid == 0) {
            mbar_wait(FULL0 + s * 8, fph[s]); fph[s] ^= 1;
            const uint32_t st = sbase + 1024 + s * STAGE;
#pragma unroll
            for (int t2 = 0; t2 < 2; t2++) {
                uint64_t ad = mk_desc(st + t2 * 16384);
                uint64_t bd = mk_desc(st + 32768 + t2 * 16384);
#pragma unroll
                for (int kk = 0; kk < 4; kk++)
                    mma_cg2(tmem, ad + kk * 2, bd + kk * 2, (i > 0) || (t2 > 0) || (kk > 0));
            }
            asm volatile("tcgen05.commit.cta_group::2.mbarrier::arrive::one.shared::cluster.multicast::cluster.b64 [%0], %1;"
                         :: "r"(MMAB0 + s * 8), "h"((uint16_t)3) : "memory");
        }
        const int j = i + NST - 1;
        if (j < NCH) {
            const int s2 = j % NST;
            if (j >= NST) { mbar_wait(MMAB0 + s2 * 8, mph[s2]); mph[s2] ^= 1; }
            fill(j);
        }
    }
    mbar_wait(MMAB0 + SLAST * 8, FINPAR);
    asm volatile("tcgen05.fence::after_thread_sync;" ::: "memory");

    {
        const int gm = m_tile * 256 + (int)rank * 128 + (wid & 3) * 32 + lane;
        float* crow = g_P + (size_t)gm * NPROJ_PAD + n_tile * 256 + (wid >> 2) * 128;
        const uint32_t cb0 = tmem + (uint32_t)((wid >> 2) * 128);
#pragma unroll
        for (int cb = 0; cb < 128; cb += 32) {
            uint32_t d[32];
            asm volatile("tcgen05.ld.sync.aligned.32x32b.x32.b32 "
                "{%0,%1,%2,%3,%4,%5,%6,%7,%8,%9,%10,%11,%12,%13,%14,%15,"
                "%16,%17,%18,%19,%20,%21,%22,%23,%24,%25,%26,%27,%28,%29,%30,%31}, [%32];"
                : "=r"(d[0]),"=r"(d[1]),"=r"(d[2]),"=r"(d[3]),"=r"(d[4]),"=r"(d[5]),"=r"(d[6]),"=r"(d[7]),
                  "=r"(d[8]),"=r"(d[9]),"=r"(d[10]),"=r"(d[11]),"=r"(d[12]),"=r"(d[13]),"=r"(d[14]),"=r"(d[15]),
                  "=r"(d[16]),"=r"(d[17]),"=r"(d[18]),"=r"(d[19]),"=r"(d[20]),"=r"(d[21]),"=r"(d[22]),"=r"(d[23]),
                  "=r"(d[24]),"=r"(d[25]),"=r"(d[26]),"=r"(d[27]),"=r"(d[28]),"=r"(d[29]),"=r"(d[30]),"=r"(d[31])
                : "r"(cb0 + cb));
            asm volatile("tcgen05.wait::ld.sync.aligned;" ::: "memory");
#pragma unroll
            for (int c = 0; c < 32; c += 4)
                *reinterpret_cast<float4*>(crow + cb + c) =
                    make_float4(__uint_as_float(d[c]), __uint_as_float(d[c+1]),
                                __uint_as_float(d[c+2]), __uint_as_float(d[c+3]));
        }
    }
    __syncthreads();
    if (tid == 0) {
        for (int s = 0; s < NST; s++) { mbar_inval(FULL0 + s * 8); mbar_inval(MMAB0 + s * 8); }
    }
    __syncthreads();
    if (wid == 0) {
        asm volatile("tcgen05.relinquish_alloc_permit.cta_group::2.sync.aligned;");
        asm volatile("tcgen05.dealloc.cta_group::2.sync.aligned.b32 %0, %1;" :: "r"(tmem), "r"(512));
    }
    cluster_sync();
#endif
}

// ---------------------------------------------------------------- main GEMM (R13-proven)
__global__ void __cluster_dims__(2, 1, 1) __launch_bounds__(256, 1)
gemm_main_kernel(float* __restrict__ Cg) {
#if defined(__CUDA_ARCH_FEAT_SM103_ALL)
    constexpr int NST = 2;
    constexpr int NCH = DIN / 64 + GEXT / 64;       // 67
    constexpr int STAGE = 98304;
    constexpr int A_HI = 0, A_LO = 16384, B_HI = 32768, B_LO = 65536;
    constexpr int SLAST = (NCH - 1) & (NST - 1);    // 0
    constexpr uint32_t FINPAR = (((NCH - 1 - SLAST) / NST + 1) - 1) & 1;  // 1

    extern __shared__ char smem[];
    const uint32_t sbase = smem_u32(smem);
    const int tid = threadIdx.x, wid = tid >> 5, lane = tid & 31;
    const uint32_t rank = ctarank();
    const int n_tile = blockIdx.x >> 1, m_tile = blockIdx.y;
    const uint32_t FULL0 = sbase + 8, MMAB0 = sbase + 40;

    if (tid == 0)
        for (int s = 0; s < NST; s++) { mbar_init(FULL0 + s * 8, 2); mbar_init(MMAB0 + s * 8, 1); }
    if (wid == 0)
        asm volatile("tcgen05.alloc.cta_group::2.sync.aligned.shared::cta.b32 [%0], %1;"
                     :: "r"(sbase), "r"(512) : "memory");
    __syncthreads();
    uint32_t tmem;
    asm volatile("ld.shared.b32 %0, [%1];" : "=r"(tmem) : "r"(sbase));
    cluster_sync();

    const int arow0 = m_tile * 256 + (int)rank * 128;
    const int brow0 = n_tile * 512 + (int)rank * 128;
    const __nv_bfloat16* Arow = g_Xp + (size_t)arow0 * KP2;
    const __nv_bfloat16* Brow = g_Wp + (size_t)brow0 * KP2;

    auto load_tile = [&](uint32_t sdst, const __nv_bfloat16* gsrc) {
#pragma unroll
        for (int p = 0; p < 4; p++) {
            int q = p * 256 + tid, r = q >> 3, c = q & 7;
            uint32_t off = (uint32_t)(r * 128 + c * 16);
            uint32_t sw = off ^ ((off >> 3) & 0x70);
            cpa16(sdst + sw, gsrc + (size_t)r * KP2 + c * 8);
        }
    };

    auto fill = [&](int chunk) {
        const uint32_t st = sbase + 1024 + (chunk & (NST - 1)) * STAGE;
        if (chunk < 64) {
            const int kb = chunk * 64;
            load_tile(st + A_HI, Arow + kb);
            load_tile(st + A_LO, Arow + kb + DIN);
#pragma unroll
            for (int h = 0; h < 2; h++) {
                const __nv_bfloat16* Bh = Brow + (size_t)(h * 256) * KP2;
                load_tile(st + B_HI + h * 16384, Bh + kb);
                load_tile(st + B_LO + h * 16384, Bh + kb + DIN);
            }
        } else {
            const int kb = EXT0 + (chunk - 64) * 64;
            load_tile(st + A_HI, Arow + kb);
#pragma unroll
            for (int h = 0; h < 2; h++)
                load_tile(st + B_HI + h * 16384, Brow + (size_t)(h * 256) * KP2 + kb);
        }
        cp_commit();
    };

    uint32_t fph[NST] = {}, mph[NST] = {};
    fill(0);
    for (int i = 0; i < NCH; i++) {
        const int s = i & (NST - 1);
        cp_wait<0>();
        __syncthreads();
        if (tid == 0) { fence_async(); mbar_arrive_rank0(FULL0 + s * 8); }
        if (rank == 0 && tid == 0) {
            mbar_wait(FULL0 + s * 8, fph[s]); fph[s] ^= 1;
            const uint32_t st = sbase + 1024 + s * STAGE;
            uint64_t ahi = mk_desc(st + A_HI), alo = mk_desc(st + A_LO);
#pragma unroll
            for (int h = 0; h < 2; h++) {
                uint64_t bhi = mk_desc(st + B_HI + h * 16384);
                uint64_t blo = mk_desc(st + B_LO + h * 16384);
                uint32_t dh = tmem + h * 256;
#pragma unroll
                for (int kk = 0; kk < 4; kk++) {
                    uint32_t en = ((i > 0) || (kk > 0)) ? 1u : 0u;
                    mma_cg2(dh, ahi + kk * 2, bhi + kk * 2, en);
                    if (i < 64) {
                        mma_cg2(dh, alo + kk * 2, bhi + kk * 2, 1u);
                        mma_cg2(dh, ahi + kk * 2, blo + kk * 2, 1u);
                    }
                }
            }
            asm volatile("tcgen05.commit.cta_group::2.mbarrier::arrive::one.shared::cluster.multicast::cluster.b64 [%0], %1;"
                         :: "r"(MMAB0 + s * 8), "h"((uint16_t)3) : "memory");
        }
        const int j = i + 1;
        if (j < NCH) {
            const int s2 = j & (NST - 1);
            if (j >= NST) { mbar_wait(MMAB0 + s2 * 8, mph[s2]); mph[s2] ^= 1; }
            fill(j);
        }
    }
    mbar_wait(MMAB0 + SLAST * 8, FINPAR);
    asm volatile("tcgen05.fence::after_thread_sync;" ::: "memory");

    // epilogue
    {
        const int gm = arow0 + (wid & 3) * 32 + lane;
        float* crow = Cg + (size_t)gm * DOUT + n_tile * 512 + (wid >> 2) * 256;
        const uint32_t cb0 = tmem + (uint32_t)((wid >> 2) * 256);
#pragma unroll
        for (int cb = 0; cb < 256; cb += 32) {
            uint32_t d[32];
            asm volatile("tcgen05.ld.sync.aligned.32x32b.x32.b32 "
                "{%0,%1,%2,%3,%4,%5,%6,%7,%8,%9,%10,%11,%12,%13,%14,%15,"
                "%16,%17,%18,%19,%20,%21,%22,%23,%24,%25,%26,%27,%28,%29,%30,%31}, [%32];"
                : "=r"(d[0]),"=r"(d[1]),"=r"(d[2]),"=r"(d[3]),"=r"(d[4]),"=r"(d[5]),"=r"(d[6]),"=r"(d[7]),
                  "=r"(d[8]),"=r"(d[9]),"=r"(d[10]),"=r"(d[11]),"=r"(d[12]),"=r"(d[13]),"=r"(d[14]),"=r"(d[15]),
                  "=r"(d[16]),"=r"(d[17]),"=r"(d[18]),"=r"(d[19]),"=r"(d[20]),"=r"(d[21]),"=r"(d[22]),"=r"(d[23]),
                  "=r"(d[24]),"=r"(d[25]),"=r"(d[26]),"=r"(d[27]),"=r"(d[28]),"=r"(d[29]),"=r"(d[30]),"=r"(d[31])
                : "r"(cb0 + cb));
            asm volatile("tcgen05.wait::ld.sync.aligned;" ::: "memory");
#pragma unroll
            for (int c = 0; c < 32; c += 4)
                *reinterpret_cast<float4*>(crow + cb + c) =
                    make_float4(__uint_as_float(d[c]), __uint_as_float(d[c+1]),
                                __uint_as_float(d[c+2]), __uint_as_float(d[c+3]));
        }
    }
    __syncthreads();
    if (tid == 0) {
        for (int s = 0; s < NST; s++) { mbar_inval(FULL0 + s * 8); mbar_inval(MMAB0 + s * 8); }
    }
    __syncthreads();
    if (wid == 0) {
        asm volatile("tcgen05.relinquish_alloc_permit.cta_group::2.sync.aligned;");
        asm volatile("tcgen05.dealloc.cta_group::2.sync.aligned.b32 %0, %1;" :: "r"(tmem), "r"(512));
    }
    cluster_sync();
#endif
}

// ---------------------------------------------------------------- launch
// Inputs (metadata order): x, W, b, Wq, Wk, A, Bm
extern "C" void kernel_launch(void* const* d_in, const int* in_sizes, int n_in,
                              void* d_out, int out_size) {
    const float* x  = (const float*)d_in[0];
    const float* W  = (const float*)d_in[1];
    const float* b  = (const float*)d_in[2];
    const float* Wq = (const float*)d_in[3];
    const float* Wk = (const float*)d_in[4];
    const float* A  = (const float*)d_in[5];
    const float* Bm = (const float*)d_in[6];
    float* out = (float*)d_out;

    constexpr int SMEM0 = 1024 + 3 * 65536;    // 197632
    constexpr int SMEM1 = 1024 + 2 * 98304;    // 197632
    cudaFuncSetAttribute(gemm_proj_kernel, cudaFuncAttributeMaxDynamicSharedMemorySize, SMEM0);
    cudaFuncSetAttribute(gemm_main_kernel, cudaFuncAttributeMaxDynamicSharedMemorySize, SMEM1);

    split_xw_kernel  <<<MTOK + DOUT, 256>>>(x, W);
    split_proj_kernel<<<(int)(((size_t)NPROJ_PAD * DIN / 4 + 255) / 256), 256>>>(Wq, Wk, A);
    pack_b2_kernel   <<<(DOUT * GEXT + 255) / 256, 256>>>(Bm, b);

    // projections P = x_hi @ [Wq;Wk;A]_hi^T  (TN=256, BK=128, NST=3)
    gemm_proj_kernel<<<dim3(2 * (NPROJ_PAD / 256), MTOK / 256), 256, SMEM0>>>();

    // routing -> G ext cols (hi only) of g_Xp
    routing_kernel<<<(MTOK * 32) / 256, 256>>>();

    // out = x @ W^T + G @ B2^T (+bias)
    gemm_main_kernel<<<dim3(2 * (DOUT / 512), MTOK / 256), 256, SMEM1>>>(out);
}